// round 7
// baseline (speedup 1.0000x reference)
#include <cuda_runtime.h>
#include <cstdint>

// ============================================================================
// Persistent 2-layer LSTM for GB300 (sm_103a) — R7.
//   Gate-major outer-product: lane owns 2 gate columns, registers hold
//   16 f32x2 accumulators (2 gates x 16 batches). Weights stream COALESCED
//   from a shared gate-major L2 image (ld.global.nc.v2.f32) — no smem
//   weights, no broadcast LDS for weights. h is the broadcast operand,
//   amortized 16 FFMA2 per 4 LDS.128.
//   Split-group pipeline: CTAs 0-63 compute layer 0, CTAs 64-127 layer 1,
//   skewed by one step. h0 rides a 4-deep global ring so B never exposes
//   its h0 wait; only B's own h1 recurrence is on the critical path.
// ============================================================================

#define NGRID 128
#define NHALF 64
#define HST   0        // staging: [16 warps][<=64 rows][16 floats] = 64 KB
#define DMB   65536    // dump B-half: [8][64][8] f32x2 = 32 KB
#define DMA   98304    // dump A-half: [8][64][8] f32x2 = 32 KB
#define SMEM_TOTAL 131072

// ------------------------- device-global scratch ---------------------------
__device__ float g_xT[1024][256][32];     // x transposed: [t][c][batch]
__device__ float g_h0[4][512][32];        // h0 ring (depth 4)
__device__ float g_h1[2][512][32];        // h1 ring (depth 2)
__device__ float g_W0T[768][2048];        // gate-major: [k][unit*4+q]
__device__ float g_W1T[1024][2048];
__device__ unsigned g_c0, g_c1, g_cbc;    // h0-done, h1-done, B-consumed

// ------------------------------ helpers ------------------------------------
static __device__ __forceinline__ void cp16(void* d, const void* s) {
    unsigned ds = (unsigned)__cvta_generic_to_shared(d);
    asm volatile("cp.async.cg.shared.global [%0], [%1], 16;" :: "r"(ds), "l"(s));
}
static __device__ __forceinline__ float sigm(float x) {
    return 1.0f / (1.0f + __expf(-x));
}
static __device__ __forceinline__ float tanh_f(float x) {
    return 1.0f - 2.0f / (__expf(2.0f * x) + 1.0f);
}
static __device__ __forceinline__ unsigned long long pkdup(float v) {
    unsigned u = __float_as_uint(v);
    unsigned long long r;
    asm("mov.b64 %0, {%1, %1};" : "=l"(r) : "r"(u));
    return r;
}
static __device__ __forceinline__ void ffma2(unsigned long long& acc,
                                             unsigned long long a,
                                             unsigned long long b) {
    asm("fma.rn.f32x2 %0, %1, %2, %0;" : "+l"(acc) : "l"(a), "l"(b));
}
static __device__ __forceinline__ unsigned long long addf2(unsigned long long a,
                                                           unsigned long long b) {
    unsigned long long r;
    asm("add.rn.f32x2 %0, %1, %2;" : "=l"(r) : "l"(a), "l"(b));
    return r;
}
// lane0 spins until *cp >= tgt, then warp proceeds
static __device__ __forceinline__ void warp_wait(unsigned* cp, unsigned tgt) {
    if ((threadIdx.x & 31) == 0) {
        unsigned v;
        for (;;) {
            asm volatile("ld.acquire.gpu.global.u32 %0, [%1];" : "=r"(v) : "l"(cp) : "memory");
            if ((int)(v - tgt) >= 0) break;
            __nanosleep(20);
        }
    }
    __syncwarp();
}

// acc2[gi*8+bp] += W[k][gate 2*lane+gi] * h2[k][bp]   (k = r0..r0+NKW)
template <int NKW>
static __device__ __forceinline__ void mm_warp(
    const float* __restrict__ Wmat, int r0, int gbase,
    const float* __restrict__ hrow0, unsigned long long acc2[16])
{
    const int lane = threadIdx.x & 31;
    const float* wp = Wmat + (size_t)r0 * 2048 + gbase + 2 * lane;
    float2 wbuf[4];
    #pragma unroll
    for (int i = 0; i < 4; i++)
        wbuf[i] = __ldg((const float2*)(wp + (size_t)i * 2048));
    const ulonglong2* hp = (const ulonglong2*)hrow0;
    #pragma unroll 4
    for (int kk = 0; kk < NKW; kk++) {
        float2 wv = wbuf[kk & 3];
        if (kk + 4 < NKW)
            wbuf[kk & 3] = __ldg((const float2*)(wp + (size_t)(kk + 4) * 2048));
        unsigned long long w2a = pkdup(wv.x);
        unsigned long long w2b = pkdup(wv.y);
        ulonglong2 hA = hp[kk * 4 + 0];
        ulonglong2 hB = hp[kk * 4 + 1];
        ulonglong2 hC = hp[kk * 4 + 2];
        ulonglong2 hD = hp[kk * 4 + 3];
        ffma2(acc2[0], w2a, hA.x);  ffma2(acc2[8],  w2b, hA.x);
        ffma2(acc2[1], w2a, hA.y);  ffma2(acc2[9],  w2b, hA.y);
        ffma2(acc2[2], w2a, hB.x);  ffma2(acc2[10], w2b, hB.x);
        ffma2(acc2[3], w2a, hB.y);  ffma2(acc2[11], w2b, hB.y);
        ffma2(acc2[4], w2a, hC.x);  ffma2(acc2[12], w2b, hC.x);
        ffma2(acc2[5], w2a, hC.y);  ffma2(acc2[13], w2b, hC.y);
        ffma2(acc2[6], w2a, hD.x);  ffma2(acc2[14], w2b, hD.x);
        ffma2(acc2[7], w2a, hD.y);  ffma2(acc2[15], w2b, hD.y);
    }
}

// --------------------------- persistent kernel -----------------------------
__global__ void __launch_bounds__(512, 1)
lstm_persist(const float* __restrict__ b0f, const float* __restrict__ b0i,
             const float* __restrict__ b0c, const float* __restrict__ b0o,
             const float* __restrict__ b1f, const float* __restrict__ b1i,
             const float* __restrict__ b1c, const float* __restrict__ b1o,
             float* __restrict__ out)
{
    extern __shared__ char smem[];
    float* hst = (float*)(smem + HST);
    unsigned long long* dmB = (unsigned long long*)(smem + DMB);
    unsigned long long* dmA = (unsigned long long*)(smem + DMA);

    const int tid  = threadIdx.x;
    const int lane = tid & 31;
    const int warp = tid >> 5;        // 0..15
    const int cta  = blockIdx.x;
    const bool isB = (cta >= NHALF);
    const int idx  = isB ? cta - NHALF : cta;   // 0..63
    const int ggi  = idx >> 1;                  // gate-group 0..31
    const int bb   = (idx & 1) << 4;            // batch base: 0 or 16
    const int gbase = ggi * 64;                 // 64 gate columns per CTA

    // finalize identity: thread (fu, fb) owns unit gu, batch bb+fb
    const int fu = tid >> 4;          // 0..15 valid when tid < 256
    const int fb = tid & 15;
    const int gu = ggi * 16 + fu;     // global unit 0..511
    float Bf = 0.f, Bi = 0.f, Bc = 0.f, Bo = 0.f;
    if (tid < 256) {
        if (!isB) { Bf = b0f[gu]; Bi = b0i[gu]; Bc = b0c[gu]; Bo = b0o[gu]; }
        else      { Bf = b1f[gu]; Bi = b1i[gu]; Bc = b1c[gu]; Bo = b1o[gu]; }
    }
    float cst = 0.0f;
    unsigned long long acc2[16];

    for (int t = 0; t < 1024; t++) {
        // ---------------- stage this warp's k-rows into smem ---------------
        if (!isB) {
            // A: K = 768 = [x(t) 256 ; h0(t-1) 512], 48 rows per warp
            const int r0 = warp * 48;
            if (t >= 4) warp_wait(&g_cbc, 64u * (t - 3));   // h0 ring safety
            if (r0 + 48 > 256) warp_wait(&g_c0, 64u * t);   // h0(t-1) ready
            #pragma unroll
            for (int it = 0; it < 2; it++) {
                int rr = lane + it * 32;
                if (rr < 48) {
                    int k = r0 + rr;
                    const float* src = (k < 256) ? &g_xT[t][k][bb]
                                                 : &g_h0[(t - 1) & 3][k - 256][bb];
                    float* dst = hst + (size_t)(warp * 48 + rr) * 16;
                    cp16(dst, src); cp16(dst + 4, src + 4);
                    cp16(dst + 8, src + 8); cp16(dst + 12, src + 12);
                }
            }
        } else {
            // B: K = 1024 = [h0(t) 512 ; h1(t-1) 512], 64 rows per warp
            const int r0 = warp * 64;
            if (r0 < 512)       warp_wait(&g_c0, 64u * (t + 1));  // h0(t)
            if (r0 + 64 > 512)  warp_wait(&g_c1, 64u * t);        // h1(t-1)
            #pragma unroll
            for (int it = 0; it < 2; it++) {
                int rr = lane + it * 32;
                int k = r0 + rr;
                const float* src = (k < 512) ? &g_h0[t & 3][k][bb]
                                             : &g_h1[(t - 1) & 1][k - 512][bb];
                float* dst = hst + (size_t)(warp * 64 + rr) * 16;
                cp16(dst, src); cp16(dst + 4, src + 4);
                cp16(dst + 8, src + 8); cp16(dst + 12, src + 12);
            }
        }
        asm volatile("cp.async.commit_group;" ::: "memory");
        asm volatile("cp.async.wait_group 0;" ::: "memory");
        __syncwarp();

        // ---------------- compute: outer-product accumulation --------------
        #pragma unroll
        for (int p = 0; p < 16; p++) acc2[p] = 0ULL;
        if (!isB) {
            mm_warp<48>(&g_W0T[0][0], warp * 48, gbase,
                        hst + (size_t)warp * 48 * 16, acc2);
        } else {
            mm_warp<64>(&g_W1T[0][0], warp * 64, gbase,
                        hst + (size_t)warp * 64 * 16, acc2);
        }

        // ---------------- 2-stage reduce across 16 warps -------------------
        if (warp >= 8) {
            int w = warp - 8;
            #pragma unroll
            for (int gi = 0; gi < 2; gi++)
                #pragma unroll
                for (int bp = 0; bp < 8; bp++)
                    dmB[((size_t)w * 64 + 2 * lane + gi) * 8 + bp] = acc2[gi * 8 + bp];
        }
        __syncthreads();
        if (warp < 8) {
            #pragma unroll
            for (int gi = 0; gi < 2; gi++)
                #pragma unroll
                for (int bp = 0; bp < 8; bp++) {
                    size_t o = ((size_t)warp * 64 + 2 * lane + gi) * 8 + bp;
                    dmA[o] = addf2(acc2[gi * 8 + bp], dmB[o]);
                }
        }
        __syncthreads();

        // ---------------- finalize: cell update + publish ------------------
        if (tid < 256) {
            const float* dm = (const float*)dmA;
            float s[4];
            #pragma unroll
            for (int q = 0; q < 4; q++) {
                int g = fu * 4 + q;
                float a = 0.f;
                #pragma unroll
                for (int w = 0; w < 8; w++)
                    a += dm[(((size_t)w * 64 + g) * 8 + (fb >> 1)) * 2 + (fb & 1)];
                s[q] = a;
            }
            float f  = sigm(s[0] + Bf);
            float ig = sigm(s[1] + Bi);
            float gg = tanh_f(s[2] + Bc);
            float o  = sigm(s[3] + Bo);
            cst = f * cst + ig * gg;
            float h = o * tanh_f(cst);
            if (!isB) {
                g_h0[t & 3][gu][bb + fb] = h;
            } else {
                g_h1[t & 1][gu][bb + fb] = h;
                out[(size_t)(bb + fb) * 524288 + (size_t)t * 512 + gu] = h;
            }
        }
        __syncthreads();
        if (tid == 0) {
            __threadfence();
            if (!isB) {
                asm volatile("red.release.gpu.global.add.u32 [%0], 1;" :: "l"(&g_c0) : "memory");
            } else {
                asm volatile("red.release.gpu.global.add.u32 [%0], 1;" :: "l"(&g_c1) : "memory");
                asm volatile("red.release.gpu.global.add.u32 [%0], 1;" :: "l"(&g_cbc) : "memory");
            }
        }
    }
}

// ------------------------------ fused prep ---------------------------------
// items: xT 8388608 | zero h0/h1 + counters 98304 | W0T 1572864 | W1T 2097152
// total = 12156928 = 47488 * 256
__global__ void prep_all(const float* __restrict__ x,
                         const float* __restrict__ W0f, const float* __restrict__ W0i,
                         const float* __restrict__ W0c, const float* __restrict__ W0o,
                         const float* __restrict__ W1f, const float* __restrict__ W1i,
                         const float* __restrict__ W1c, const float* __restrict__ W1o)
{
    long idx = (long)blockIdx.x * blockDim.x + threadIdx.x;
    if (idx < 8388608L) {                                   // x transpose
        int b = (int)(idx & 31);
        int c = (int)((idx >> 5) & 255);
        int t = (int)(idx >> 13);
        g_xT[t][c][b] = x[(size_t)b * 262144 + (size_t)t * 256 + c];
        return;
    }
    idx -= 8388608L;
    if (idx < 98304L) {                                     // zero state + counters
        if (idx == 0) { g_c0 = 0u; g_c1 = 0u; g_cbc = 0u; }
        if (idx < 65536L) (&g_h0[0][0][0])[idx] = 0.f;
        else              (&g_h1[0][0][0])[idx - 65536L] = 0.f;
        return;
    }
    idx -= 98304L;
    if (idx < 1572864L) {                                   // W0T [768][2048]
        int k = (int)(idx >> 11);
        int g = (int)(idx & 2047);
        int u = g >> 2, q = g & 3;
        const float* W = (q == 0) ? W0f : (q == 1) ? W0i : (q == 2) ? W0c : W0o;
        g_W0T[k][g] = W[(size_t)u * 768 + k];
        return;
    }
    idx -= 1572864L;
    if (idx < 2097152L) {                                   // W1T [1024][2048]
        int k = (int)(idx >> 11);
        int g = (int)(idx & 2047);
        int u = g >> 2, q = g & 3;
        const float* W = (q == 0) ? W1f : (q == 1) ? W1i : (q == 2) ? W1c : W1o;
        g_W1T[k][g] = W[(size_t)u * 1024 + k];
    }
}

// ------------------------------- launcher ----------------------------------
extern "C" void kernel_launch(void* const* d_in, const int* in_sizes, int n_in,
                              void* d_out, int out_size)
{
    const float* x   = (const float*)d_in[0];
    const float* W0f = (const float*)d_in[1];
    const float* b0f = (const float*)d_in[2];
    const float* W0i = (const float*)d_in[3];
    const float* b0i = (const float*)d_in[4];
    const float* W0c = (const float*)d_in[5];
    const float* b0c = (const float*)d_in[6];
    const float* W0o = (const float*)d_in[7];
    const float* b0o = (const float*)d_in[8];
    const float* W1f = (const float*)d_in[9];
    const float* b1f = (const float*)d_in[10];
    const float* W1i = (const float*)d_in[11];
    const float* b1i = (const float*)d_in[12];
    const float* W1c = (const float*)d_in[13];
    const float* b1c = (const float*)d_in[14];
    const float* W1o = (const float*)d_in[15];
    const float* b1o = (const float*)d_in[16];
    float* out = (float*)d_out;

    cudaFuncSetAttribute(lstm_persist,
                         cudaFuncAttributeMaxDynamicSharedMemorySize, SMEM_TOTAL);

    prep_all<<<47488, 256>>>(x, W0f, W0i, W0c, W0o, W1f, W1i, W1c, W1o);
    lstm_persist<<<NGRID, 512, SMEM_TOTAL>>>(b0f, b0i, b0c, b0o,
                                             b1f, b1i, b1c, b1o, out);
}